// round 12
// baseline (speedup 1.0000x reference)
#include <cuda_runtime.h>
#include <cstdint>

// EdgeBlock: out = LN( relu( [n[s]; n[r]; e] @ W1 + b1 ) @ W2 + b2 )
// R12: barrier-free dataflow. No CTA-wide __syncthreads after init.
//  - A staged per warp-PAIR (2 warps sharing wm) in private double-buffered
//    smem via cp.async; pair-scoped named barriers (bar.sync id,64).
//  - B/W2 fragments via LDG.128 straight from gmem packed in fragment order
//    (warp request = contiguous 512B). L2-resident, L1-shared across warps.
//  - H in its own smem region; GEMM2 needs only one pair barrier.
//
// CTA = 128 edges, 256 threads, 8 warps 4(M)x2(N), warp tile 32x64.
// GEMM1: K=384, 12 chunks of 32. GEMM2: K=128, 4 chunks of 32.

#define CTA_M   128
#define THREADS 256

#define A_STR  36
#define H_STR  132

// smem float offsets
#define OFF_AW   0        // 4 pairs x (2 bufs x 32 x 36) = 9216 floats
#define PAIR_A_FL 2304
#define OFF_H    9216     // [128][132] = 16896 -> ends 26112
#define OFF_PRM  26112    // b1,b2,gamma,beta (512)
#define OFF_PS   26624    // LN partials (512)
#define SMEM_FLOATS 27136
#define SMEM_BYTES  (SMEM_FLOATS * 4)   // 108544 -> 2 CTAs/SM

// packed weights: per k32-chunk 4096 floats; float4 index within chunk =
// ks*256 + half*128 + q*32 + tg*8 + g  (warp request contiguous for fixed q)
__device__ uint32_t g_W1p[12 * 4096];
__device__ uint32_t g_W2p[4 * 4096];

__device__ __forceinline__ uint32_t f2tf(float f) {
    uint32_t u;
    asm("cvt.rna.tf32.f32 %0, %1;" : "=r"(u) : "f"(f));
    return u;
}
__device__ __forceinline__ uint32_t smem_u32(const void* p) {
    uint32_t a;
    asm("{ .reg .u64 t; cvta.to.shared.u64 t, %1; cvt.u32.u64 %0, t; }" : "=r"(a) : "l"(p));
    return a;
}
__device__ __forceinline__ void cp16(uint32_t dst, const void* src) {
    asm volatile("cp.async.cg.shared.global [%0], [%1], 16;" :: "r"(dst), "l"(src));
}
#define CP_COMMIT() asm volatile("cp.async.commit_group;" ::: "memory")
#define CP_WAIT0()  asm volatile("cp.async.wait_group 0;" ::: "memory")
#define CP_WAIT1()  asm volatile("cp.async.wait_group 1;" ::: "memory")
#define BARP(id)    asm volatile("bar.sync %0, 64;" :: "r"(id) : "memory")

__device__ __forceinline__ void mma8(float* d,
                                     uint32_t a0, uint32_t a1, uint32_t a2, uint32_t a3,
                                     uint32_t b0, uint32_t b1) {
    asm volatile(
        "mma.sync.aligned.m16n8k8.row.col.f32.tf32.tf32.f32 "
        "{%0,%1,%2,%3}, {%4,%5,%6,%7}, {%8,%9}, {%0,%1,%2,%3};"
        : "+f"(d[0]), "+f"(d[1]), "+f"(d[2]), "+f"(d[3])
        : "r"(a0), "r"(a1), "r"(a2), "r"(a3), "r"(b0), "r"(b1));
}

// ---------------- prepass: permute + cvt weights (LDG-coalesced order) ------
__global__ void pack_weights(const float* __restrict__ W1, const float* __restrict__ W2) {
    int i = blockIdx.x * 256 + threadIdx.x;
    const float* src;
    uint32_t* dst;
    int k, n;
    if (i < 384 * 128) {
        k = i >> 7; n = i & 127; src = W1; dst = g_W1p;
    } else {
        int i2 = i - 384 * 128;
        if (i2 >= 128 * 128) return;
        k = i2 >> 7; n = i2 & 127; src = W2; dst = g_W2p;
    }
    const int chunk = k >> 5;
    const int kk    = k & 31;
    const int ks    = kk >> 3;
    const int tg    = kk & 3;
    const int p     = (kk >> 2) & 1;
    const int half  = n >> 6;
    const int g     = n & 7;
    const int j     = (n & 63) >> 3;
    const int q     = j >> 1;
    const int e     = (j & 1) * 2 + p;
    const int dest  = chunk * 4096 +
                      (ks * 256 + half * 128 + q * 32 + tg * 8 + g) * 4 + e;
    dst[dest] = f2tf(src[(size_t)k * 128 + n]);
}

// ---------------- main kernel ----------------
__global__ __launch_bounds__(THREADS, 2)
void edge_block_mma(const float* __restrict__ node_attr,
                    const float* __restrict__ edge_attr,
                    const int*   __restrict__ senders,
                    const int*   __restrict__ receivers,
                    const float* __restrict__ b1,
                    const float* __restrict__ b2,
                    const float* __restrict__ ln_g,
                    const float* __restrict__ ln_b,
                    float* __restrict__ out,
                    int E)
{
    extern __shared__ float smem[];
    float* prm = smem + OFF_PRM;
    float* ps  = smem + OFF_PS;

    const uint32_t sbase = smem_u32(smem);

    const int tid   = threadIdx.x;
    const int lane  = tid & 31;
    const int wid   = tid >> 5;
    const int g     = lane >> 2;
    const int tig   = lane & 3;
    const int wm    = (wid >> 1) * 32;
    const int wn    = (wid & 1) * 64;
    const int wc    = wid & 1;
    const int pairid= wid >> 1;
    const int barid = pairid + 1;     // named barrier ids 1..4
    const int eb    = blockIdx.x * CTA_M;

    if (tid < 128) {
        prm[tid]       = b1[tid];
        prm[128 + tid] = b2[tid];
        prm[256 + tid] = ln_g[tid];
        prm[384 + tid] = ln_b[tid];
    }

    // pair-staging identity: 64 threads/pair, 2 per row, 16 floats each
    const int pairlane = lane + ((wid & 1) << 5);   // 0..63
    const int srow  = pairlane >> 1;                 // 0..31 (pair-local row)
    const int shalf = pairlane & 1;
    int eg = eb + wm + srow;
    if (eg >= E) eg = E - 1;
    const int sidx = senders[eg];
    const int ridx = receivers[eg];
    const float* base_s = node_attr + (size_t)sidx * 128;
    const float* base_r = node_attr + (size_t)ridx * 128;
    const float* base_e = edge_attr + (size_t)eg  * 128;

    const uint32_t dstA[2] = {
        sbase + (OFF_AW + pairid * PAIR_A_FL +        srow * A_STR + shalf * 16) * 4u,
        sbase + (OFF_AW + pairid * PAIR_A_FL + 1152 + srow * A_STR + shalf * 16) * 4u };

    auto issue_a = [&](int ch) {
        const int buf = ch & 1;
        const int sel = ch >> 2;
        const float* ab = (sel == 0) ? base_s : ((sel == 1) ? base_r : base_e);
        const float* asrc = ab + (ch & 3) * 32 + shalf * 16;
        #pragma unroll
        for (int i = 0; i < 4; ++i)
            cp16(dstA[buf] + i * 16, asrc + i * 4);
        CP_COMMIT();
    };

    __syncthreads();   // prm visible; ONLY CTA-wide barrier in the kernel

    float acc[2][8][4];
    #pragma unroll
    for (int i = 0; i < 2; ++i)
        #pragma unroll
        for (int j = 0; j < 8; ++j)
            #pragma unroll
            for (int c = 0; c < 4; ++c) acc[i][j][c] = 0.f;

    // prologue: 2 chunks in flight
    issue_a(0);
    issue_a(1);

    const int halfsel = wn >> 6;
    const uint4* W1q = reinterpret_cast<const uint4*>(g_W1p) + halfsel * 128 + tig * 8 + g;
    const uint4* W2q = reinterpret_cast<const uint4*>(g_W2p) + halfsel * 128 + tig * 8 + g;
    const float* Apair = smem + OFF_AW + pairid * PAIR_A_FL + g * A_STR;

    // ======================= GEMM1: 12 chunks of k=32 =======================
    #pragma unroll 2
    for (int ch = 0; ch < 12; ++ch) {
        if (ch < 11) CP_WAIT1(); else CP_WAIT0();
        BARP(barid);              // partner's A(ch) writes visible

        const float* Af = Apair + (ch & 1) * 1152;
        const uint4* Bc = W1q + ch * 1024;
        #pragma unroll
        for (int ks = 0; ks < 4; ++ks) {
            const int ka = ks * 8 + tig;
            uint4 r0 = Bc[ks * 256 +  0];
            uint4 r1 = Bc[ks * 256 + 32];
            uint4 r2 = Bc[ks * 256 + 64];
            uint4 r3 = Bc[ks * 256 + 96];
            uint32_t av[2][4];
            #pragma unroll
            for (int i = 0; i < 2; ++i) {
                av[i][0] = f2tf(Af[(16 * i)     * A_STR + ka]);
                av[i][1] = f2tf(Af[(16 * i + 8) * A_STR + ka]);
                av[i][2] = f2tf(Af[(16 * i)     * A_STR + ka + 4]);
                av[i][3] = f2tf(Af[(16 * i + 8) * A_STR + ka + 4]);
            }
            #pragma unroll
            for (int i = 0; i < 2; ++i) {
                mma8(acc[i][0], av[i][0], av[i][1], av[i][2], av[i][3], r0.x, r0.y);
                mma8(acc[i][1], av[i][0], av[i][1], av[i][2], av[i][3], r0.z, r0.w);
                mma8(acc[i][2], av[i][0], av[i][1], av[i][2], av[i][3], r1.x, r1.y);
                mma8(acc[i][3], av[i][0], av[i][1], av[i][2], av[i][3], r1.z, r1.w);
                mma8(acc[i][4], av[i][0], av[i][1], av[i][2], av[i][3], r2.x, r2.y);
                mma8(acc[i][5], av[i][0], av[i][1], av[i][2], av[i][3], r2.z, r2.w);
                mma8(acc[i][6], av[i][0], av[i][1], av[i][2], av[i][3], r3.x, r3.y);
                mma8(acc[i][7], av[i][0], av[i][1], av[i][2], av[i][3], r3.z, r3.w);
            }
        }
        BARP(barid);              // partner's A(ch) reads done
        if (ch < 10) issue_a(ch + 2);   // overwrite buf (ch&1)
    }

    // ---- H = relu(acc + b1) -> H[m][k] tf32 (uint2 pairs), pair-private rows
    {
        uint32_t* Hsu = reinterpret_cast<uint32_t*>(smem + OFF_H);
        float b1v[8][2];
        #pragma unroll
        for (int j = 0; j < 8; ++j) {
            b1v[j][0] = prm[wn + 8 * j + 2 * tig];
            b1v[j][1] = prm[wn + 8 * j + 2 * tig + 1];
        }
        #pragma unroll
        for (int i = 0; i < 2; ++i) {
            const int r0 = wm + 16 * i + g;
            #pragma unroll
            for (int j = 0; j < 8; ++j) {
                const int n0 = wn + 8 * j + 2 * tig;
                uint2 h01 = make_uint2(f2tf(fmaxf(acc[i][j][0] + b1v[j][0], 0.f)),
                                       f2tf(fmaxf(acc[i][j][1] + b1v[j][1], 0.f)));
                uint2 h23 = make_uint2(f2tf(fmaxf(acc[i][j][2] + b1v[j][0], 0.f)),
                                       f2tf(fmaxf(acc[i][j][3] + b1v[j][1], 0.f)));
                *reinterpret_cast<uint2*>(&Hsu[r0 * H_STR + n0])       = h01;
                *reinterpret_cast<uint2*>(&Hsu[(r0 + 8) * H_STR + n0]) = h23;
            }
        }
    }

    #pragma unroll
    for (int i = 0; i < 2; ++i)
        #pragma unroll
        for (int j = 0; j < 8; ++j)
            #pragma unroll
            for (int c = 0; c < 4; ++c) acc[i][j][c] = 0.f;

    BARP(barid);   // partner's H half visible (pair writes/reads same 32 rows)

    // ======================= GEMM2: 4 chunks of k=32, zero staging sync =====
    {
        const uint32_t* Hf = reinterpret_cast<const uint32_t*>(smem + OFF_H)
                             + (wm + g) * H_STR;
        #pragma unroll
        for (int ch = 0; ch < 4; ++ch) {
            const uint4* Bc = W2q + ch * 1024;
            #pragma unroll
            for (int ks = 0; ks < 4; ++ks) {
                const int ka = ch * 32 + ks * 8 + tig;
                uint4 r0 = Bc[ks * 256 +  0];
                uint4 r1 = Bc[ks * 256 + 32];
                uint4 r2 = Bc[ks * 256 + 64];
                uint4 r3 = Bc[ks * 256 + 96];
                uint32_t av[2][4];
                #pragma unroll
                for (int i = 0; i < 2; ++i) {
                    av[i][0] = Hf[(16 * i)     * H_STR + ka];
                    av[i][1] = Hf[(16 * i + 8) * H_STR + ka];
                    av[i][2] = Hf[(16 * i)     * H_STR + ka + 4];
                    av[i][3] = Hf[(16 * i + 8) * H_STR + ka + 4];
                }
                #pragma unroll
                for (int i = 0; i < 2; ++i) {
                    mma8(acc[i][0], av[i][0], av[i][1], av[i][2], av[i][3], r0.x, r0.y);
                    mma8(acc[i][1], av[i][0], av[i][1], av[i][2], av[i][3], r0.z, r0.w);
                    mma8(acc[i][2], av[i][0], av[i][1], av[i][2], av[i][3], r1.x, r1.y);
                    mma8(acc[i][3], av[i][0], av[i][1], av[i][2], av[i][3], r1.z, r1.w);
                    mma8(acc[i][4], av[i][0], av[i][1], av[i][2], av[i][3], r2.x, r2.y);
                    mma8(acc[i][5], av[i][0], av[i][1], av[i][2], av[i][3], r2.z, r2.w);
                    mma8(acc[i][6], av[i][0], av[i][1], av[i][2], av[i][3], r3.x, r3.y);
                    mma8(acc[i][7], av[i][0], av[i][1], av[i][2], av[i][3], r3.z, r3.w);
                }
            }
        }
    }

    // ======================= LayerNorm epilogue (pair-scoped) ===============
    float b2v[8][2], gv[8][2], bev[8][2];
    #pragma unroll
    for (int j = 0; j < 8; ++j) {
        const int n0 = wn + 8 * j + 2 * tig;
        b2v[j][0] = prm[128 + n0]; b2v[j][1] = prm[128 + n0 + 1];
        gv[j][0]  = prm[256 + n0]; gv[j][1]  = prm[256 + n0 + 1];
        bev[j][0] = prm[384 + n0]; bev[j][1] = prm[384 + n0 + 1];
    }

    #pragma unroll
    for (int i = 0; i < 2; ++i) {
        float s0 = 0.f, q0 = 0.f, s1 = 0.f, q1 = 0.f;
        #pragma unroll
        for (int j = 0; j < 8; ++j) {
            float v0 = acc[i][j][0] + b2v[j][0];
            float v1 = acc[i][j][1] + b2v[j][1];
            float v2 = acc[i][j][2] + b2v[j][0];
            float v3 = acc[i][j][3] + b2v[j][1];
            acc[i][j][0] = v0; acc[i][j][1] = v1; acc[i][j][2] = v2; acc[i][j][3] = v3;
            s0 += v0 + v1; q0 += v0 * v0 + v1 * v1;
            s1 += v2 + v3; q1 += v2 * v2 + v3 * v3;
        }
        #pragma unroll
        for (int m = 1; m < 4; m <<= 1) {
            s0 += __shfl_xor_sync(0xffffffffu, s0, m);
            q0 += __shfl_xor_sync(0xffffffffu, q0, m);
            s1 += __shfl_xor_sync(0xffffffffu, s1, m);
            q1 += __shfl_xor_sync(0xffffffffu, q1, m);
        }
        if (tig == 0) {
            const int r0 = wm + 16 * i + g;
            ps[wc * 128 + r0]           = s0;
            ps[wc * 128 + r0 + 8]       = s1;
            ps[256 + wc * 128 + r0]     = q0;
            ps[256 + wc * 128 + r0 + 8] = q1;
        }
    }
    BARP(barid);   // partner's partials visible (pair rows disjoint from others)

    #pragma unroll
    for (int i = 0; i < 2; ++i) {
        const int r0 = wm + 16 * i + g;
        const int r1 = r0 + 8;
        float s0 = ps[r0] + ps[128 + r0];
        float q0 = ps[256 + r0] + ps[384 + r0];
        float s1 = ps[r1] + ps[128 + r1];
        float q1 = ps[256 + r1] + ps[384 + r1];
        const float mu0 = s0 * (1.f / 128.f);
        const float mu1 = s1 * (1.f / 128.f);
        const float rs0 = rsqrtf(q0 * (1.f / 128.f) - mu0 * mu0 + 1e-5f);
        const float rs1 = rsqrtf(q1 * (1.f / 128.f) - mu1 * mu1 + 1e-5f);
        const int eg0 = eb + r0;
        const int eg1 = eb + r1;
        if (eg0 < E) {
            float* orow = out + (size_t)eg0 * 128;
            #pragma unroll
            for (int j = 0; j < 8; ++j) {
                const int n0 = wn + 8 * j + 2 * tig;
                float o0 = (acc[i][j][0] - mu0) * rs0 * gv[j][0] + bev[j][0];
                float o1 = (acc[i][j][1] - mu0) * rs0 * gv[j][1] + bev[j][1];
                *reinterpret_cast<float2*>(orow + n0) = make_float2(o0, o1);
            }
        }
        if (eg1 < E) {
            float* orow = out + (size_t)eg1 * 128;
            #pragma unroll
            for (int j = 0; j < 8; ++j) {
                const int n0 = wn + 8 * j + 2 * tig;
                float o2 = (acc[i][j][2] - mu1) * rs1 * gv[j][0] + bev[j][0];
                float o3 = (acc[i][j][3] - mu1) * rs1 * gv[j][1] + bev[j][1];
                *reinterpret_cast<float2*>(orow + n0) = make_float2(o2, o3);
            }
        }
    }
}

extern "C" void kernel_launch(void* const* d_in, const int* in_sizes, int n_in,
                              void* d_out, int out_size)
{
    (void)n_in; (void)out_size;
    const float* node_attr = (const float*)d_in[0];
    const float* edge_attr = (const float*)d_in[1];
    const int*   senders   = (const int*)  d_in[2];
    const int*   receivers = (const int*)  d_in[3];
    const float* W1        = (const float*)d_in[4];
    const float* b1        = (const float*)d_in[5];
    const float* W2        = (const float*)d_in[6];
    const float* b2        = (const float*)d_in[7];
    const float* ln_gamma  = (const float*)d_in[8];
    const float* ln_beta   = (const float*)d_in[9];
    float* out = (float*)d_out;

    const int E = in_sizes[2];

    pack_weights<<<256, 256>>>(W1, W2);

    cudaFuncSetAttribute(edge_block_mma,
                         cudaFuncAttributeMaxDynamicSharedMemorySize, SMEM_BYTES);

    const int grid = (E + CTA_M - 1) / CTA_M;
    edge_block_mma<<<grid, THREADS, SMEM_BYTES>>>(
        node_attr, edge_attr, senders, receivers,
        b1, b2, ln_gamma, ln_beta, out, E);
}

// round 14
// speedup vs baseline: 1.6051x; 1.6051x over previous
#include <cuda_runtime.h>
#include <cstdint>

// EdgeBlock: out = LN( relu( [n[s]; n[r]; e] @ W1 + b1 ) @ W2 + b2 )
// R14 = R11 protocol (proven correct) with CTA_M=64 / warp tile 16x64 so
// acc drops to 32 regs -> 3 CTAs/SM (6 warps/SMSP, +50% latency hiding).
// smem 70.7KB/CTA. Weight chunks streamed via cp.async.bulk as in R11.
//
// CTA = 64 edges, 256 threads, 8 warps 4(M)x2(N), warp tile 16x64.
// GEMM1: K=384, 12 chunks of 32. GEMM2: K=128, 4 chunks of 32 (W2 streamed).

#define CTA_M   64
#define THREADS 256

#define A_STR  36
#define H_STR  132
#define B_CHUNK_FL 4224   // 32 blocks * 132 floats
#define B_CHUNK_BYTES (B_CHUNK_FL * 4)   // 16896

// smem float offsets
#define OFF_H    0        // [64][132] = 8448 (phase 2)
#define OFF_A0   0        // [64][36] = 2304 (phase 1, aliases H)
#define OFF_A1   2304     // ends 4608 (< 8448)
#define OFF_B0   8448     // 4224
#define OFF_B1   12672    // ends 16896
#define OFF_PRM  16896    // b1,b2,gamma,beta (512)
#define OFF_PS   17408    // LN partials (256)
#define OFF_MBAR 17664    // 2 mbarriers (16 bytes)
#define SMEM_FLOATS 17672
#define SMEM_BYTES  (SMEM_FLOATS * 4)    // 70688 -> 3 CTAs/SM

__device__ uint32_t g_W1p[12 * B_CHUNK_FL];
__device__ uint32_t g_W2p[4 * B_CHUNK_FL];

__device__ __forceinline__ uint32_t f2tf(float f) {
    uint32_t u;
    asm("cvt.rna.tf32.f32 %0, %1;" : "=r"(u) : "f"(f));
    return u;
}
__device__ __forceinline__ uint32_t smem_u32(const void* p) {
    uint32_t a;
    asm("{ .reg .u64 t; cvta.to.shared.u64 t, %1; cvt.u32.u64 %0, t; }" : "=r"(a) : "l"(p));
    return a;
}
__device__ __forceinline__ void cp16(uint32_t dst, const void* src) {
    asm volatile("cp.async.cg.shared.global [%0], [%1], 16;" :: "r"(dst), "l"(src));
}
#define CP_COMMIT() asm volatile("cp.async.commit_group;" ::: "memory")
#define CP_WAIT0()  asm volatile("cp.async.wait_group 0;" ::: "memory")

#define MBAR_INIT(mbar, cnt) \
    asm volatile("mbarrier.init.shared.b64 [%0], %1;" :: "r"((uint32_t)(mbar)), "r"((uint32_t)(cnt)) : "memory")
#define MBAR_ARRIVE_EXPECT(mbar, bytes) \
    asm volatile("mbarrier.arrive.expect_tx.shared.b64 _, [%0], %1;" :: "r"((uint32_t)(mbar)), "r"((uint32_t)(bytes)) : "memory")
#define BULK_G2S(dst, src, bytes, mbar) \
    asm volatile("cp.async.bulk.shared::cta.global.mbarrier::complete_tx::bytes [%0], [%1], %2, [%3];" \
                 :: "r"((uint32_t)(dst)), "l"(src), "r"((uint32_t)(bytes)), "r"((uint32_t)(mbar)) : "memory")

#define MBAR_WAIT(mbar, parity) do { \
    uint32_t _m = (uint32_t)(mbar); \
    uint32_t _p = (uint32_t)(parity); \
    uint32_t _done; \
    asm volatile( \
        "{\n\t.reg .pred p;\n\t" \
        "mbarrier.try_wait.parity.acquire.cta.shared::cta.b64 p, [%1], %2;\n\t" \
        "selp.b32 %0, 1, 0, p;\n\t}" \
        : "=r"(_done) : "r"(_m), "r"(_p) : "memory"); \
    if (!_done) { \
        asm volatile( \
            "{\n\t.reg .pred P1;\n\t" \
            "WAIT_LOOP_%=:\n\t" \
            "mbarrier.try_wait.parity.acquire.cta.shared::cta.b64 P1, [%0], %1, 0x989680;\n\t" \
            "@P1 bra.uni WAIT_DONE_%=;\n\t" \
            "bra.uni WAIT_LOOP_%=;\n\t" \
            "WAIT_DONE_%=:\n\t}" \
            :: "r"(_m), "r"(_p) : "memory"); \
    } \
} while(0)

__device__ __forceinline__ void mma8(float* d,
                                     uint32_t a0, uint32_t a1, uint32_t a2, uint32_t a3,
                                     uint32_t b0, uint32_t b1) {
    asm volatile(
        "mma.sync.aligned.m16n8k8.row.col.f32.tf32.tf32.f32 "
        "{%0,%1,%2,%3}, {%4,%5,%6,%7}, {%8,%9}, {%0,%1,%2,%3};"
        : "+f"(d[0]), "+f"(d[1]), "+f"(d[2]), "+f"(d[3])
        : "r"(a0), "r"(a1), "r"(a2), "r"(a3), "r"(b0), "r"(b1));
}

// ---------------- prepass: permute + cvt weights (R11 fragment order) -------
__global__ void pack_weights(const float* __restrict__ W1, const float* __restrict__ W2) {
    int i = blockIdx.x * 256 + threadIdx.x;
    const float* src;
    uint32_t* dst;
    int k, n;
    if (i < 384 * 128) {
        k = i >> 7; n = i & 127; src = W1; dst = g_W1p;
    } else {
        int i2 = i - 384 * 128;
        if (i2 >= 128 * 128) return;
        k = i2 >> 7; n = i2 & 127; src = W2; dst = g_W2p;
    }
    const int chunk = k >> 5;
    const int kk    = k & 31;
    const int ks    = kk >> 3;
    const int tg    = kk & 3;
    const int p     = (kk >> 2) & 1;
    const int half  = n >> 6;
    const int g     = n & 7;
    const int j     = (n & 63) >> 3;
    const int dest  = chunk * B_CHUNK_FL +
                      ((ks * 2 + half) * 4 + tg) * 132 + g * 16 + j * 2 + p;
    dst[dest] = f2tf(src[(size_t)k * 128 + n]);
}

// ---------------- main kernel ----------------
__global__ __launch_bounds__(THREADS, 3)
void edge_block_mma(const float* __restrict__ node_attr,
                    const float* __restrict__ edge_attr,
                    const int*   __restrict__ senders,
                    const int*   __restrict__ receivers,
                    const float* __restrict__ b1,
                    const float* __restrict__ b2,
                    const float* __restrict__ ln_g,
                    const float* __restrict__ ln_b,
                    float* __restrict__ out,
                    int E)
{
    extern __shared__ float smem[];
    float* prm = smem + OFF_PRM;
    float* ps  = smem + OFF_PS;

    const uint32_t sbase = smem_u32(smem);
    const uint32_t mb0 = sbase + OFF_MBAR * 4u;
    const uint32_t mb1 = mb0 + 8u;

    const int tid  = threadIdx.x;
    const int lane = tid & 31;
    const int wid  = tid >> 5;
    const int g    = lane >> 2;
    const int tig  = lane & 3;
    const int wm   = (wid >> 1) * 16;   // 4 M-warps x 16 rows
    const int wn   = (wid & 1) * 64;
    const int wc   = wid & 1;
    const int eb   = blockIdx.x * CTA_M;

    if (tid < 128) {
        prm[tid]       = b1[tid];
        prm[128 + tid] = b2[tid];
        prm[256 + tid] = ln_g[tid];
        prm[384 + tid] = ln_b[tid];
    }
    if (tid == 0) { MBAR_INIT(mb0, 1); MBAR_INIT(mb1, 1); }

    // gather identity: 4 threads per row, 8 floats each
    const int arow = tid >> 2;          // 0..63
    const int aq   = tid & 3;           // quarter of 32-float chunk
    int eg = eb + arow;
    if (eg >= E) eg = E - 1;
    const int sidx = senders[eg];
    const int ridx = receivers[eg];
    const float* base_s = node_attr + (size_t)sidx * 128;
    const float* base_r = node_attr + (size_t)ridx * 128;
    const float* base_e = edge_attr + (size_t)eg  * 128;

    const uint32_t offA[2] = {
        sbase + (OFF_A0 + arow * A_STR + aq * 8) * 4u,
        sbase + (OFF_A1 + arow * A_STR + aq * 8) * 4u };
    const uint32_t bdst[2] = { sbase + OFF_B0 * 4u, sbase + OFF_B1 * 4u };
    const uint32_t mbar[2] = { mb0, mb1 };

    auto issue_a = [&](int ch) {
        const int buf = ch & 1;
        const int sel = ch >> 2;
        const float* ab = (sel == 0) ? base_s : ((sel == 1) ? base_r : base_e);
        const float* asrc = ab + (ch & 3) * 32 + aq * 8;
        cp16(offA[buf], asrc);
        cp16(offA[buf] + 16, asrc + 4);
        CP_COMMIT();
    };

    __syncthreads();   // mbarrier init + prm visible

    float acc[8][4];
    #pragma unroll
    for (int j = 0; j < 8; ++j)
        #pragma unroll
        for (int c = 0; c < 4; ++c) acc[j][c] = 0.f;

    // prologue: chunk 0
    issue_a(0);
    if (tid == 0) {
        MBAR_ARRIVE_EXPECT(mb0, B_CHUNK_BYTES);
        BULK_G2S(bdst[0], g_W1p, B_CHUNK_BYTES, mb0);
    }

    const int halfsel = wn >> 6;
    int ph0 = 0, ph1 = 0;

    // ======================= GEMM1: 12 chunks of k=32 =======================
    #pragma unroll 2
    for (int ch = 0; ch < 12; ++ch) {
        const int b = ch & 1;
        CP_WAIT0();               // this thread's A(ch) arrived
        __syncthreads();          // all A(ch) visible; buf b^1 reads done
        if (ch < 11) {
            issue_a(ch + 1);
            if (tid == 0) {
                MBAR_ARRIVE_EXPECT(mbar[b ^ 1], B_CHUNK_BYTES);
                BULK_G2S(bdst[b ^ 1], g_W1p + (size_t)(ch + 1) * B_CHUNK_FL,
                         B_CHUNK_BYTES, mbar[b ^ 1]);
            }
        } else {
            if (tid == 0) {       // W2 chunk 0 -> buf0
                MBAR_ARRIVE_EXPECT(mb0, B_CHUNK_BYTES);
                BULK_G2S(bdst[0], g_W2p, B_CHUNK_BYTES, mb0);
            }
        }
        if (b == 0) { MBAR_WAIT(mb0, ph0); ph0 ^= 1; }
        else        { MBAR_WAIT(mb1, ph1); ph1 ^= 1; }

        const float* Af = smem + (b ? OFF_A1 : OFF_A0) + (wm + g) * A_STR;
        const uint4* Bq = reinterpret_cast<const uint4*>(smem + (b ? OFF_B1 : OFF_B0));
        #pragma unroll
        for (int ks = 0; ks < 4; ++ks) {
            const int ka = ks * 8 + tig;
            const uint4* bp = Bq + (size_t)((ks * 2 + halfsel) * 4 + tig) * 33 + g * 4;
            uint4 r0 = bp[0], r1 = bp[1], r2 = bp[2], r3 = bp[3];
            uint32_t a0 = f2tf(Af[ka]);
            uint32_t a1 = f2tf(Af[8 * A_STR + ka]);
            uint32_t a2 = f2tf(Af[ka + 4]);
            uint32_t a3 = f2tf(Af[8 * A_STR + ka + 4]);
            mma8(acc[0], a0, a1, a2, a3, r0.x, r0.y);
            mma8(acc[1], a0, a1, a2, a3, r0.z, r0.w);
            mma8(acc[2], a0, a1, a2, a3, r1.x, r1.y);
            mma8(acc[3], a0, a1, a2, a3, r1.z, r1.w);
            mma8(acc[4], a0, a1, a2, a3, r2.x, r2.y);
            mma8(acc[5], a0, a1, a2, a3, r2.z, r2.w);
            mma8(acc[6], a0, a1, a2, a3, r3.x, r3.y);
            mma8(acc[7], a0, a1, a2, a3, r3.z, r3.w);
        }
    }
    __syncthreads();   // GEMM1 reads done; A region free for H

    // ---- H = relu(acc + b1) -> H[m][k] tf32 (uint2 pairs; W2(0) in flight)
    {
        uint32_t* Hsu = reinterpret_cast<uint32_t*>(smem + OFF_H);
        const int r0 = wm + g;
        #pragma unroll
        for (int j = 0; j < 8; ++j) {
            const int n0 = wn + 8 * j + 2 * tig;
            float bj0 = prm[n0], bj1 = prm[n0 + 1];
            uint2 h01 = make_uint2(f2tf(fmaxf(acc[j][0] + bj0, 0.f)),
                                   f2tf(fmaxf(acc[j][1] + bj1, 0.f)));
            uint2 h23 = make_uint2(f2tf(fmaxf(acc[j][2] + bj0, 0.f)),
                                   f2tf(fmaxf(acc[j][3] + bj1, 0.f)));
            *reinterpret_cast<uint2*>(&Hsu[r0 * H_STR + n0])       = h01;
            *reinterpret_cast<uint2*>(&Hsu[(r0 + 8) * H_STR + n0]) = h23;
        }
    }

    #pragma unroll
    for (int j = 0; j < 8; ++j)
        #pragma unroll
        for (int c = 0; c < 4; ++c) acc[j][c] = 0.f;

    // ======================= GEMM2: 4 chunks of k=32 =======================
    #pragma unroll 2
    for (int ch = 0; ch < 4; ++ch) {
        const int b = ch & 1;
        __syncthreads();          // H writes visible (ch0); prev buf reads done
        if (ch < 3 && tid == 0) {
            MBAR_ARRIVE_EXPECT(mbar[b ^ 1], B_CHUNK_BYTES);
            BULK_G2S(bdst[b ^ 1], g_W2p + (size_t)(ch + 1) * B_CHUNK_FL,
                     B_CHUNK_BYTES, mbar[b ^ 1]);
        }
        if (b == 0) { MBAR_WAIT(mb0, ph0); ph0 ^= 1; }
        else        { MBAR_WAIT(mb1, ph1); ph1 ^= 1; }

        const uint32_t* Hf = reinterpret_cast<const uint32_t*>(smem + OFF_H)
                             + (wm + g) * H_STR + ch * 32;
        const uint4* Bq = reinterpret_cast<const uint4*>(smem + (b ? OFF_B1 : OFF_B0));
        #pragma unroll
        for (int ks = 0; ks < 4; ++ks) {
            const int ka = ks * 8 + tig;
            const uint4* bp = Bq + (size_t)((ks * 2 + halfsel) * 4 + tig) * 33 + g * 4;
            uint4 r0 = bp[0], r1 = bp[1], r2 = bp[2], r3 = bp[3];
            uint32_t a0 = Hf[ka];
            uint32_t a1 = Hf[8 * H_STR + ka];
            uint32_t a2 = Hf[ka + 4];
            uint32_t a3 = Hf[8 * H_STR + ka + 4];
            mma8(acc[0], a0, a1, a2, a3, r0.x, r0.y);
            mma8(acc[1], a0, a1, a2, a3, r0.z, r0.w);
            mma8(acc[2], a0, a1, a2, a3, r1.x, r1.y);
            mma8(acc[3], a0, a1, a2, a3, r1.z, r1.w);
            mma8(acc[4], a0, a1, a2, a3, r2.x, r2.y);
            mma8(acc[5], a0, a1, a2, a3, r2.z, r2.w);
            mma8(acc[6], a0, a1, a2, a3, r3.x, r3.y);
            mma8(acc[7], a0, a1, a2, a3, r3.z, r3.w);
        }
    }

    // ======================= LayerNorm epilogue =======================
    {
        float s0 = 0.f, q0 = 0.f, s1 = 0.f, q1 = 0.f;
        #pragma unroll
        for (int j = 0; j < 8; ++j) {
            const int n0 = wn + 8 * j + 2 * tig;
            float v0 = acc[j][0] + prm[128 + n0];
            float v1 = acc[j][1] + prm[128 + n0 + 1];
            float v2 = acc[j][2] + prm[128 + n0];
            float v3 = acc[j][3] + prm[128 + n0 + 1];
            acc[j][0] = v0; acc[j][1] = v1; acc[j][2] = v2; acc[j][3] = v3;
            s0 += v0 + v1; q0 += v0 * v0 + v1 * v1;
            s1 += v2 + v3; q1 += v2 * v2 + v3 * v3;
        }
        #pragma unroll
        for (int m = 1; m < 4; m <<= 1) {
            s0 += __shfl_xor_sync(0xffffffffu, s0, m);
            q0 += __shfl_xor_sync(0xffffffffu, q0, m);
            s1 += __shfl_xor_sync(0xffffffffu, s1, m);
            q1 += __shfl_xor_sync(0xffffffffu, q1, m);
        }
        if (tig == 0) {
            const int r0 = wm + g;
            ps[wc * 64 + r0]           = s0;
            ps[wc * 64 + r0 + 8]       = s1;
            ps[128 + wc * 64 + r0]     = q0;
            ps[128 + wc * 64 + r0 + 8] = q1;
        }
    }
    __syncthreads();

    {
        const int r0 = wm + g;
        const int r1 = r0 + 8;
        float s0 = ps[r0] + ps[64 + r0];
        float q0 = ps[128 + r0] + ps[192 + r0];
        float s1 = ps[r1] + ps[64 + r1];
        float q1 = ps[128 + r1] + ps[192 + r1];
        const float mu0 = s0 * (1.f / 128.f);
        const float mu1 = s1 * (1.f / 128.f);
        const float rs0 = rsqrtf(q0 * (1.f / 128.f) - mu0 * mu0 + 1e-5f);
        const float rs1 = rsqrtf(q1 * (1.f / 128.f) - mu1 * mu1 + 1e-5f);
        const int eg0 = eb + r0;
        const int eg1 = eb + r1;
        if (eg0 < E) {
            float* orow = out + (size_t)eg0 * 128;
            #pragma unroll
            for (int j = 0; j < 8; ++j) {
                const int n0 = wn + 8 * j + 2 * tig;
                float o0 = (acc[j][0] - mu0) * rs0 * prm[256 + n0]     + prm[384 + n0];
                float o1 = (acc[j][1] - mu0) * rs0 * prm[256 + n0 + 1] + prm[384 + n0 + 1];
                *reinterpret_cast<float2*>(orow + n0) = make_float2(o0, o1);
            }
        }
        if (eg1 < E) {
            float* orow = out + (size_t)eg1 * 128;
            #pragma unroll
            for (int j = 0; j < 8; ++j) {
                const int n0 = wn + 8 * j + 2 * tig;
                float o2 = (acc[j][2] - mu1) * rs1 * prm[256 + n0]     + prm[384 + n0];
                float o3 = (acc[j][3] - mu1) * rs1 * prm[256 + n0 + 1] + prm[384 + n0 + 1];
                *reinterpret_cast<float2*>(orow + n0) = make_float2(o2, o3);
            }
        }
    }
}

extern "C" void kernel_launch(void* const* d_in, const int* in_sizes, int n_in,
                              void* d_out, int out_size)
{
    (void)n_in; (void)out_size;
    const float* node_attr = (const float*)d_in[0];
    const float* edge_attr = (const float*)d_in[1];
    const int*   senders   = (const int*)  d_in[2];
    const int*   receivers = (const int*)  d_in[3];
    const float* W1        = (const float*)d_in[4];
    const float* b1        = (const float*)d_in[5];
    const float* W2        = (const float*)d_in[6];
    const float* b2        = (const float*)d_in[7];
    const float* ln_gamma  = (const float*)d_in[8];
    const float* ln_beta   = (const float*)d_in[9];
    float* out = (float*)d_out;

    const int E = in_sizes[2];

    pack_weights<<<256, 256>>>(W1, W2);

    cudaFuncSetAttribute(edge_block_mma,
                         cudaFuncAttributeMaxDynamicSharedMemorySize, SMEM_BYTES);

    const int grid = (E + CTA_M - 1) / CTA_M;
    edge_block_mma<<<grid, THREADS, SMEM_BYTES>>>(
        node_attr, edge_attr, senders, receivers,
        b1, b2, ln_gamma, ln_beta, out, E);
}

// round 15
// speedup vs baseline: 1.6293x; 1.0151x over previous
#include <cuda_runtime.h>
#include <cstdint>

// EdgeBlock: out = LN( relu( [n[s]; n[r]; e] @ W1 + b1 ) @ W2 + b2 )
// R15 = R14 (CTA_M=64, 3 CTAs/SM, R11 protocol) with warp grid reshaped
// 4(M)x2(N) -> 2(M)x4(N): warp tile 32x32. Cuts per-chunk smem fragment
// traffic ~20% (B loads halve: each warp needs only a j-quarter of its
// half; A loads double but are cheap scalars). acc stays 32 regs.
//
// CTA = 64 edges, 256 threads, 8 warps 2(M)x4(N), warp tile 32x32.
// GEMM1: K=384, 12 chunks of 32. GEMM2: K=128, 4 chunks of 32 (W2 streamed).

#define CTA_M   64
#define THREADS 256

#define A_STR  36
#define H_STR  132
#define B_CHUNK_FL 4224   // 32 blocks * 132 floats
#define B_CHUNK_BYTES (B_CHUNK_FL * 4)   // 16896

// smem float offsets
#define OFF_H    0        // [64][132] = 8448 (phase 2)
#define OFF_A0   0        // [64][36] = 2304 (phase 1, aliases H)
#define OFF_A1   2304     // ends 4608 (< 8448)
#define OFF_B0   8448     // 4224
#define OFF_B1   12672    // ends 16896
#define OFF_PRM  16896    // b1,b2,gamma,beta (512)
#define OFF_PS   17408    // LN partials: sums[4][64] + sqs[4][64] (512)
#define OFF_MBAR 17920    // 2 mbarriers (16 bytes)
#define SMEM_FLOATS 17928
#define SMEM_BYTES  (SMEM_FLOATS * 4)    // 71712 -> 3 CTAs/SM

__device__ uint32_t g_W1p[12 * B_CHUNK_FL];
__device__ uint32_t g_W2p[4 * B_CHUNK_FL];

__device__ __forceinline__ uint32_t f2tf(float f) {
    uint32_t u;
    asm("cvt.rna.tf32.f32 %0, %1;" : "=r"(u) : "f"(f));
    return u;
}
__device__ __forceinline__ uint32_t smem_u32(const void* p) {
    uint32_t a;
    asm("{ .reg .u64 t; cvta.to.shared.u64 t, %1; cvt.u32.u64 %0, t; }" : "=r"(a) : "l"(p));
    return a;
}
__device__ __forceinline__ void cp16(uint32_t dst, const void* src) {
    asm volatile("cp.async.cg.shared.global [%0], [%1], 16;" :: "r"(dst), "l"(src));
}
#define CP_COMMIT() asm volatile("cp.async.commit_group;" ::: "memory")
#define CP_WAIT0()  asm volatile("cp.async.wait_group 0;" ::: "memory")

#define MBAR_INIT(mbar, cnt) \
    asm volatile("mbarrier.init.shared.b64 [%0], %1;" :: "r"((uint32_t)(mbar)), "r"((uint32_t)(cnt)) : "memory")
#define MBAR_ARRIVE_EXPECT(mbar, bytes) \
    asm volatile("mbarrier.arrive.expect_tx.shared.b64 _, [%0], %1;" :: "r"((uint32_t)(mbar)), "r"((uint32_t)(bytes)) : "memory")
#define BULK_G2S(dst, src, bytes, mbar) \
    asm volatile("cp.async.bulk.shared::cta.global.mbarrier::complete_tx::bytes [%0], [%1], %2, [%3];" \
                 :: "r"((uint32_t)(dst)), "l"(src), "r"((uint32_t)(bytes)), "r"((uint32_t)(mbar)) : "memory")

#define MBAR_WAIT(mbar, parity) do { \
    uint32_t _m = (uint32_t)(mbar); \
    uint32_t _p = (uint32_t)(parity); \
    uint32_t _done; \
    asm volatile( \
        "{\n\t.reg .pred p;\n\t" \
        "mbarrier.try_wait.parity.acquire.cta.shared::cta.b64 p, [%1], %2;\n\t" \
        "selp.b32 %0, 1, 0, p;\n\t}" \
        : "=r"(_done) : "r"(_m), "r"(_p) : "memory"); \
    if (!_done) { \
        asm volatile( \
            "{\n\t.reg .pred P1;\n\t" \
            "WAIT_LOOP_%=:\n\t" \
            "mbarrier.try_wait.parity.acquire.cta.shared::cta.b64 P1, [%0], %1, 0x989680;\n\t" \
            "@P1 bra.uni WAIT_DONE_%=;\n\t" \
            "bra.uni WAIT_LOOP_%=;\n\t" \
            "WAIT_DONE_%=:\n\t}" \
            :: "r"(_m), "r"(_p) : "memory"); \
    } \
} while(0)

__device__ __forceinline__ void mma8(float* d,
                                     uint32_t a0, uint32_t a1, uint32_t a2, uint32_t a3,
                                     uint32_t b0, uint32_t b1) {
    asm volatile(
        "mma.sync.aligned.m16n8k8.row.col.f32.tf32.tf32.f32 "
        "{%0,%1,%2,%3}, {%4,%5,%6,%7}, {%8,%9}, {%0,%1,%2,%3};"
        : "+f"(d[0]), "+f"(d[1]), "+f"(d[2]), "+f"(d[3])
        : "r"(a0), "r"(a1), "r"(a2), "r"(a3), "r"(b0), "r"(b1));
}

// ---------------- prepass: permute + cvt weights (R11 fragment order) -------
__global__ void pack_weights(const float* __restrict__ W1, const float* __restrict__ W2) {
    int i = blockIdx.x * 256 + threadIdx.x;
    const float* src;
    uint32_t* dst;
    int k, n;
    if (i < 384 * 128) {
        k = i >> 7; n = i & 127; src = W1; dst = g_W1p;
    } else {
        int i2 = i - 384 * 128;
        if (i2 >= 128 * 128) return;
        k = i2 >> 7; n = i2 & 127; src = W2; dst = g_W2p;
    }
    const int chunk = k >> 5;
    const int kk    = k & 31;
    const int ks    = kk >> 3;
    const int tg    = kk & 3;
    const int p     = (kk >> 2) & 1;
    const int half  = n >> 6;
    const int g     = n & 7;
    const int j     = (n & 63) >> 3;
    const int dest  = chunk * B_CHUNK_FL +
                      ((ks * 2 + half) * 4 + tg) * 132 + g * 16 + j * 2 + p;
    dst[dest] = f2tf(src[(size_t)k * 128 + n]);
}

// ---------------- main kernel ----------------
__global__ __launch_bounds__(THREADS, 3)
void edge_block_mma(const float* __restrict__ node_attr,
                    const float* __restrict__ edge_attr,
                    const int*   __restrict__ senders,
                    const int*   __restrict__ receivers,
                    const float* __restrict__ b1,
                    const float* __restrict__ b2,
                    const float* __restrict__ ln_g,
                    const float* __restrict__ ln_b,
                    float* __restrict__ out,
                    int E)
{
    extern __shared__ float smem[];
    float* prm = smem + OFF_PRM;
    float* ps  = smem + OFF_PS;

    const uint32_t sbase = smem_u32(smem);
    const uint32_t mb0 = sbase + OFF_MBAR * 4u;
    const uint32_t mb1 = mb0 + 8u;

    const int tid  = threadIdx.x;
    const int lane = tid & 31;
    const int wid  = tid >> 5;
    const int g    = lane >> 2;
    const int tig  = lane & 3;
    const int wm   = (wid >> 2) * 32;   // 2 M-warps x 32 rows
    const int wn   = (wid & 3) * 32;    // 4 N-warps x 32 cols
    const int wc   = wid & 3;
    const int eb   = blockIdx.x * CTA_M;

    if (tid < 128) {
        prm[tid]       = b1[tid];
        prm[128 + tid] = b2[tid];
        prm[256 + tid] = ln_g[tid];
        prm[384 + tid] = ln_b[tid];
    }
    if (tid == 0) { MBAR_INIT(mb0, 1); MBAR_INIT(mb1, 1); }

    // gather identity: 4 threads per row, 8 floats each
    const int arow = tid >> 2;          // 0..63
    const int aq   = tid & 3;
    int eg = eb + arow;
    if (eg >= E) eg = E - 1;
    const int sidx = senders[eg];
    const int ridx = receivers[eg];
    const float* base_s = node_attr + (size_t)sidx * 128;
    const float* base_r = node_attr + (size_t)ridx * 128;
    const float* base_e = edge_attr + (size_t)eg  * 128;

    const uint32_t offA[2] = {
        sbase + (OFF_A0 + arow * A_STR + aq * 8) * 4u,
        sbase + (OFF_A1 + arow * A_STR + aq * 8) * 4u };
    const uint32_t bdst[2] = { sbase + OFF_B0 * 4u, sbase + OFF_B1 * 4u };
    const uint32_t mbar[2] = { mb0, mb1 };

    auto issue_a = [&](int ch) {
        const int buf = ch & 1;
        const int sel = ch >> 2;
        const float* ab = (sel == 0) ? base_s : ((sel == 1) ? base_r : base_e);
        const float* asrc = ab + (ch & 3) * 32 + aq * 8;
        cp16(offA[buf], asrc);
        cp16(offA[buf] + 16, asrc + 4);
        CP_COMMIT();
    };

    __syncthreads();   // mbarrier init + prm visible

    float acc[2][4][4];
    #pragma unroll
    for (int i = 0; i < 2; ++i)
        #pragma unroll
        for (int j = 0; j < 4; ++j)
            #pragma unroll
            for (int c = 0; c < 4; ++c) acc[i][j][c] = 0.f;

    // prologue: chunk 0
    issue_a(0);
    if (tid == 0) {
        MBAR_ARRIVE_EXPECT(mb0, B_CHUNK_BYTES);
        BULK_G2S(bdst[0], g_W1p, B_CHUNK_BYTES, mb0);
    }

    const int halfsel = wn >> 6;              // which 64-wide half
    const int jsel    = (wn & 32) >> 5;       // which j-quarter (0: j0-3, 1: j4-7)
    int ph0 = 0, ph1 = 0;

    // ======================= GEMM1: 12 chunks of k=32 =======================
    #pragma unroll 2
    for (int ch = 0; ch < 12; ++ch) {
        const int b = ch & 1;
        CP_WAIT0();
        __syncthreads();
        if (ch < 11) {
            issue_a(ch + 1);
            if (tid == 0) {
                MBAR_ARRIVE_EXPECT(mbar[b ^ 1], B_CHUNK_BYTES);
                BULK_G2S(bdst[b ^ 1], g_W1p + (size_t)(ch + 1) * B_CHUNK_FL,
                         B_CHUNK_BYTES, mbar[b ^ 1]);
            }
        } else {
            if (tid == 0) {
                MBAR_ARRIVE_EXPECT(mb0, B_CHUNK_BYTES);
                BULK_G2S(bdst[0], g_W2p, B_CHUNK_BYTES, mb0);
            }
        }
        if (b == 0) { MBAR_WAIT(mb0, ph0); ph0 ^= 1; }
        else        { MBAR_WAIT(mb1, ph1); ph1 ^= 1; }

        const float* Af = smem + (b ? OFF_A1 : OFF_A0) + (wm + g) * A_STR;
        const uint4* Bq = reinterpret_cast<const uint4*>(smem + (b ? OFF_B1 : OFF_B0));
        #pragma unroll
        for (int ks = 0; ks < 4; ++ks) {
            const int ka = ks * 8 + tig;
            const uint4* bp = Bq + (size_t)((ks * 2 + halfsel) * 4 + tig) * 33
                              + g * 4 + jsel * 2;
            uint4 r0 = bp[0], r1 = bp[1];
            uint32_t av[2][4];
            #pragma unroll
            for (int i = 0; i < 2; ++i) {
                av[i][0] = f2tf(Af[(16 * i)     * A_STR + ka]);
                av[i][1] = f2tf(Af[(16 * i + 8) * A_STR + ka]);
                av[i][2] = f2tf(Af[(16 * i)     * A_STR + ka + 4]);
                av[i][3] = f2tf(Af[(16 * i + 8) * A_STR + ka + 4]);
            }
            #pragma unroll
            for (int i = 0; i < 2; ++i) {
                mma8(acc[i][0], av[i][0], av[i][1], av[i][2], av[i][3], r0.x, r0.y);
                mma8(acc[i][1], av[i][0], av[i][1], av[i][2], av[i][3], r0.z, r0.w);
                mma8(acc[i][2], av[i][0], av[i][1], av[i][2], av[i][3], r1.x, r1.y);
                mma8(acc[i][3], av[i][0], av[i][1], av[i][2], av[i][3], r1.z, r1.w);
            }
        }
    }
    __syncthreads();   // GEMM1 reads done; A region free for H

    // ---- H = relu(acc + b1) -> H[m][k] tf32 (uint2 pairs; W2(0) in flight)
    {
        uint32_t* Hsu = reinterpret_cast<uint32_t*>(smem + OFF_H);
        #pragma unroll
        for (int i = 0; i < 2; ++i) {
            const int r0 = wm + 16 * i + g;
            #pragma unroll
            for (int j = 0; j < 4; ++j) {
                const int n0 = wn + 8 * j + 2 * tig;
                float bj0 = prm[n0], bj1 = prm[n0 + 1];
                uint2 h01 = make_uint2(f2tf(fmaxf(acc[i][j][0] + bj0, 0.f)),
                                       f2tf(fmaxf(acc[i][j][1] + bj1, 0.f)));
                uint2 h23 = make_uint2(f2tf(fmaxf(acc[i][j][2] + bj0, 0.f)),
                                       f2tf(fmaxf(acc[i][j][3] + bj1, 0.f)));
                *reinterpret_cast<uint2*>(&Hsu[r0 * H_STR + n0])       = h01;
                *reinterpret_cast<uint2*>(&Hsu[(r0 + 8) * H_STR + n0]) = h23;
            }
        }
    }

    #pragma unroll
    for (int i = 0; i < 2; ++i)
        #pragma unroll
        for (int j = 0; j < 4; ++j)
            #pragma unroll
            for (int c = 0; c < 4; ++c) acc[i][j][c] = 0.f;

    // ======================= GEMM2: 4 chunks of k=32 =======================
    #pragma unroll 2
    for (int ch = 0; ch < 4; ++ch) {
        const int b = ch & 1;
        __syncthreads();
        if (ch < 3 && tid == 0) {
            MBAR_ARRIVE_EXPECT(mbar[b ^ 1], B_CHUNK_BYTES);
            BULK_G2S(bdst[b ^ 1], g_W2p + (size_t)(ch + 1) * B_CHUNK_FL,
                     B_CHUNK_BYTES, mbar[b ^ 1]);
        }
        if (b == 0) { MBAR_WAIT(mb0, ph0); ph0 ^= 1; }
        else        { MBAR_WAIT(mb1, ph1); ph1 ^= 1; }

        const uint32_t* Hf = reinterpret_cast<const uint32_t*>(smem + OFF_H)
                             + (wm + g) * H_STR + ch * 32;
        const uint4* Bq = reinterpret_cast<const uint4*>(smem + (b ? OFF_B1 : OFF_B0));
        #pragma unroll
        for (int ks = 0; ks < 4; ++ks) {
            const int ka = ks * 8 + tig;
            const uint4* bp = Bq + (size_t)((ks * 2 + halfsel) * 4 + tig) * 33
                              + g * 4 + jsel * 2;
            uint4 r0 = bp[0], r1 = bp[1];
            uint32_t av[2][4];
            #pragma unroll
            for (int i = 0; i < 2; ++i) {
                av[i][0] = Hf[(16 * i)     * H_STR + ka];
                av[i][1] = Hf[(16 * i + 8) * H_STR + ka];
                av[i][2] = Hf[(16 * i)     * H_STR + ka + 4];
                av[i][3] = Hf[(16 * i + 8) * H_STR + ka + 4];
            }
            #pragma unroll
            for (int i = 0; i < 2; ++i) {
                mma8(acc[i][0], av[i][0], av[i][1], av[i][2], av[i][3], r0.x, r0.y);
                mma8(acc[i][1], av[i][0], av[i][1], av[i][2], av[i][3], r0.z, r0.w);
                mma8(acc[i][2], av[i][0], av[i][1], av[i][2], av[i][3], r1.x, r1.y);
                mma8(acc[i][3], av[i][0], av[i][1], av[i][2], av[i][3], r1.z, r1.w);
            }
        }
    }

    // ======================= LayerNorm epilogue (4 column partials) =========
    #pragma unroll
    for (int i = 0; i < 2; ++i) {
        float s0 = 0.f, q0 = 0.f, s1 = 0.f, q1 = 0.f;
        #pragma unroll
        for (int j = 0; j < 4; ++j) {
            const int n0 = wn + 8 * j + 2 * tig;
            float v0 = acc[i][j][0] + prm[128 + n0];
            float v1 = acc[i][j][1] + prm[128 + n0 + 1];
            float v2 = acc[i][j][2] + prm[128 + n0];
            float v3 = acc[i][j][3] + prm[128 + n0 + 1];
            acc[i][j][0] = v0; acc[i][j][1] = v1; acc[i][j][2] = v2; acc[i][j][3] = v3;
            s0 += v0 + v1; q0 += v0 * v0 + v1 * v1;
            s1 += v2 + v3; q1 += v2 * v2 + v3 * v3;
        }
        #pragma unroll
        for (int m = 1; m < 4; m <<= 1) {
            s0 += __shfl_xor_sync(0xffffffffu, s0, m);
            q0 += __shfl_xor_sync(0xffffffffu, q0, m);
            s1 += __shfl_xor_sync(0xffffffffu, s1, m);
            q1 += __shfl_xor_sync(0xffffffffu, q1, m);
        }
        if (tig == 0) {
            const int r0 = wm + 16 * i + g;
            ps[wc * 64 + r0]           = s0;
            ps[wc * 64 + r0 + 8]       = s1;
            ps[256 + wc * 64 + r0]     = q0;
            ps[256 + wc * 64 + r0 + 8] = q1;
        }
    }
    __syncthreads();

    #pragma unroll
    for (int i = 0; i < 2; ++i) {
        const int r0 = wm + 16 * i + g;
        const int r1 = r0 + 8;
        float s0 = ps[r0] + ps[64 + r0] + ps[128 + r0] + ps[192 + r0];
        float q0 = ps[256 + r0] + ps[320 + r0] + ps[384 + r0] + ps[448 + r0];
        float s1 = ps[r1] + ps[64 + r1] + ps[128 + r1] + ps[192 + r1];
        float q1 = ps[256 + r1] + ps[320 + r1] + ps[384 + r1] + ps[448 + r1];
        const float mu0 = s0 * (1.f / 128.f);
        const float mu1 = s1 * (1.f / 128.f);
        const float rs0 = rsqrtf(q0 * (1.f / 128.f) - mu0 * mu0 + 1e-5f);
        const float rs1 = rsqrtf(q1 * (1.f / 128.f) - mu1 * mu1 + 1e-5f);
        const int eg0 = eb + r0;
        const int eg1 = eb + r1;
        if (eg0 < E) {
            float* orow = out + (size_t)eg0 * 128;
            #pragma unroll
            for (int j = 0; j < 4; ++j) {
                const int n0 = wn + 8 * j + 2 * tig;
                float o0 = (acc[i][j][0] - mu0) * rs0 * prm[256 + n0]     + prm[384 + n0];
                float o1 = (acc[i][j][1] - mu0) * rs0 * prm[256 + n0 + 1] + prm[384 + n0 + 1];
                *reinterpret_cast<float2*>(orow + n0) = make_float2(o0, o1);
            }
        }
        if (eg1 < E) {
            float* orow = out + (size_t)eg1 * 128;
            #pragma unroll
            for (int j = 0; j < 4; ++j) {
                const int n0 = wn + 8 * j + 2 * tig;
                float o2 = (acc[i][j][2] - mu1) * rs1 * prm[256 + n0]     + prm[384 + n0];
                float o3 = (acc[i][j][3] - mu1) * rs1 * prm[256 + n0 + 1] + prm[384 + n0 + 1];
                *reinterpret_cast<float2*>(orow + n0) = make_float2(o2, o3);
            }
        }
    }
}

extern "C" void kernel_launch(void* const* d_in, const int* in_sizes, int n_in,
                              void* d_out, int out_size)
{
    (void)n_in; (void)out_size;
    const float* node_attr = (const float*)d_in[0];
    const float* edge_attr = (const float*)d_in[1];
    const int*   senders   = (const int*)  d_in[2];
    const int*   receivers = (const int*)  d_in[3];
    const float* W1        = (const float*)d_in[4];
    const float* b1        = (const float*)d_in[5];
    const float* W2        = (const float*)d_in[6];
    const float* b2        = (const float*)d_in[7];
    const float* ln_gamma  = (const float*)d_in[8];
    const float* ln_beta   = (const float*)d_in[9];
    float* out = (float*)d_out;

    const int E = in_sizes[2];

    pack_weights<<<256, 256>>>(W1, W2);

    cudaFuncSetAttribute(edge_block_mma,
                         cudaFuncAttributeMaxDynamicSharedMemorySize, SMEM_BYTES);

    const int grid = (E + CTA_M - 1) / CTA_M;
    edge_block_mma<<<grid, THREADS, SMEM_BYTES>>>(
        node_attr, edge_attr, senders, receivers,
        b1, b2, ln_gamma, ln_beta, out, E);
}

// round 16
// speedup vs baseline: 1.7004x; 1.0436x over previous
#include <cuda_runtime.h>
#include <cstdint>

// EdgeBlock: out = LN( relu( [n[s]; n[r]; e] @ W1 + b1 ) @ W2 + b2 )
// R16 = R15 (CTA_M=64, warp grid 2(M)x4(N), 3 CTAs/SM, R11 protocol) with
// the A-side cvt.rna.tf32 removed: raw fp32 bits are fed to the tf32 MMA,
// which truncates to tf32 in hardware (CUTLASS "fastest" tf32 mode).
// B/W2/H remain rna-rounded via the prepass / H store.
//
// CTA = 64 edges, 256 threads, 8 warps 2(M)x4(N), warp tile 32x32.
// GEMM1: K=384, 12 chunks of 32. GEMM2: K=128, 4 chunks of 32 (W2 streamed).

#define CTA_M   64
#define THREADS 256

#define A_STR  36
#define H_STR  132
#define B_CHUNK_FL 4224   // 32 blocks * 132 floats
#define B_CHUNK_BYTES (B_CHUNK_FL * 4)   // 16896

// smem float offsets
#define OFF_H    0        // [64][132] = 8448 (phase 2)
#define OFF_A0   0        // [64][36] = 2304 (phase 1, aliases H)
#define OFF_A1   2304     // ends 4608 (< 8448)
#define OFF_B0   8448     // 4224
#define OFF_B1   12672    // ends 16896
#define OFF_PRM  16896    // b1,b2,gamma,beta (512)
#define OFF_PS   17408    // LN partials: sums[4][64] + sqs[4][64] (512)
#define OFF_MBAR 17920    // 2 mbarriers (16 bytes)
#define SMEM_FLOATS 17928
#define SMEM_BYTES  (SMEM_FLOATS * 4)    // 71712 -> 3 CTAs/SM

__device__ uint32_t g_W1p[12 * B_CHUNK_FL];
__device__ uint32_t g_W2p[4 * B_CHUNK_FL];

__device__ __forceinline__ uint32_t f2tf(float f) {
    uint32_t u;
    asm("cvt.rna.tf32.f32 %0, %1;" : "=r"(u) : "f"(f));
    return u;
}
__device__ __forceinline__ uint32_t smem_u32(const void* p) {
    uint32_t a;
    asm("{ .reg .u64 t; cvta.to.shared.u64 t, %1; cvt.u32.u64 %0, t; }" : "=r"(a) : "l"(p));
    return a;
}
__device__ __forceinline__ void cp16(uint32_t dst, const void* src) {
    asm volatile("cp.async.cg.shared.global [%0], [%1], 16;" :: "r"(dst), "l"(src));
}
#define CP_COMMIT() asm volatile("cp.async.commit_group;" ::: "memory")
#define CP_WAIT0()  asm volatile("cp.async.wait_group 0;" ::: "memory")

#define MBAR_INIT(mbar, cnt) \
    asm volatile("mbarrier.init.shared.b64 [%0], %1;" :: "r"((uint32_t)(mbar)), "r"((uint32_t)(cnt)) : "memory")
#define MBAR_ARRIVE_EXPECT(mbar, bytes) \
    asm volatile("mbarrier.arrive.expect_tx.shared.b64 _, [%0], %1;" :: "r"((uint32_t)(mbar)), "r"((uint32_t)(bytes)) : "memory")
#define BULK_G2S(dst, src, bytes, mbar) \
    asm volatile("cp.async.bulk.shared::cta.global.mbarrier::complete_tx::bytes [%0], [%1], %2, [%3];" \
                 :: "r"((uint32_t)(dst)), "l"(src), "r"((uint32_t)(bytes)), "r"((uint32_t)(mbar)) : "memory")

#define MBAR_WAIT(mbar, parity) do { \
    uint32_t _m = (uint32_t)(mbar); \
    uint32_t _p = (uint32_t)(parity); \
    uint32_t _done; \
    asm volatile( \
        "{\n\t.reg .pred p;\n\t" \
        "mbarrier.try_wait.parity.acquire.cta.shared::cta.b64 p, [%1], %2;\n\t" \
        "selp.b32 %0, 1, 0, p;\n\t}" \
        : "=r"(_done) : "r"(_m), "r"(_p) : "memory"); \
    if (!_done) { \
        asm volatile( \
            "{\n\t.reg .pred P1;\n\t" \
            "WAIT_LOOP_%=:\n\t" \
            "mbarrier.try_wait.parity.acquire.cta.shared::cta.b64 P1, [%0], %1, 0x989680;\n\t" \
            "@P1 bra.uni WAIT_DONE_%=;\n\t" \
            "bra.uni WAIT_LOOP_%=;\n\t" \
            "WAIT_DONE_%=:\n\t}" \
            :: "r"(_m), "r"(_p) : "memory"); \
    } \
} while(0)

__device__ __forceinline__ void mma8(float* d,
                                     uint32_t a0, uint32_t a1, uint32_t a2, uint32_t a3,
                                     uint32_t b0, uint32_t b1) {
    asm volatile(
        "mma.sync.aligned.m16n8k8.row.col.f32.tf32.tf32.f32 "
        "{%0,%1,%2,%3}, {%4,%5,%6,%7}, {%8,%9}, {%0,%1,%2,%3};"
        : "+f"(d[0]), "+f"(d[1]), "+f"(d[2]), "+f"(d[3])
        : "r"(a0), "r"(a1), "r"(a2), "r"(a3), "r"(b0), "r"(b1));
}

// ---------------- prepass: permute + cvt weights (R11 fragment order) -------
__global__ void pack_weights(const float* __restrict__ W1, const float* __restrict__ W2) {
    int i = blockIdx.x * 256 + threadIdx.x;
    const float* src;
    uint32_t* dst;
    int k, n;
    if (i < 384 * 128) {
        k = i >> 7; n = i & 127; src = W1; dst = g_W1p;
    } else {
        int i2 = i - 384 * 128;
        if (i2 >= 128 * 128) return;
        k = i2 >> 7; n = i2 & 127; src = W2; dst = g_W2p;
    }
    const int chunk = k >> 5;
    const int kk    = k & 31;
    const int ks    = kk >> 3;
    const int tg    = kk & 3;
    const int p     = (kk >> 2) & 1;
    const int half  = n >> 6;
    const int g     = n & 7;
    const int j     = (n & 63) >> 3;
    const int dest  = chunk * B_CHUNK_FL +
                      ((ks * 2 + half) * 4 + tg) * 132 + g * 16 + j * 2 + p;
    dst[dest] = f2tf(src[(size_t)k * 128 + n]);
}

// ---------------- main kernel ----------------
__global__ __launch_bounds__(THREADS, 3)
void edge_block_mma(const float* __restrict__ node_attr,
                    const float* __restrict__ edge_attr,
                    const int*   __restrict__ senders,
                    const int*   __restrict__ receivers,
                    const float* __restrict__ b1,
                    const float* __restrict__ b2,
                    const float* __restrict__ ln_g,
                    const float* __restrict__ ln_b,
                    float* __restrict__ out,
                    int E)
{
    extern __shared__ float smem[];
    float* prm = smem + OFF_PRM;
    float* ps  = smem + OFF_PS;

    const uint32_t sbase = smem_u32(smem);
    const uint32_t mb0 = sbase + OFF_MBAR * 4u;
    const uint32_t mb1 = mb0 + 8u;

    const int tid  = threadIdx.x;
    const int lane = tid & 31;
    const int wid  = tid >> 5;
    const int g    = lane >> 2;
    const int tig  = lane & 3;
    const int wm   = (wid >> 2) * 32;   // 2 M-warps x 32 rows
    const int wn   = (wid & 3) * 32;    // 4 N-warps x 32 cols
    const int wc   = wid & 3;
    const int eb   = blockIdx.x * CTA_M;

    if (tid < 128) {
        prm[tid]       = b1[tid];
        prm[128 + tid] = b2[tid];
        prm[256 + tid] = ln_g[tid];
        prm[384 + tid] = ln_b[tid];
    }
    if (tid == 0) { MBAR_INIT(mb0, 1); MBAR_INIT(mb1, 1); }

    // gather identity: 4 threads per row, 8 floats each
    const int arow = tid >> 2;          // 0..63
    const int aq   = tid & 3;
    int eg = eb + arow;
    if (eg >= E) eg = E - 1;
    const int sidx = senders[eg];
    const int ridx = receivers[eg];
    const float* base_s = node_attr + (size_t)sidx * 128;
    const float* base_r = node_attr + (size_t)ridx * 128;
    const float* base_e = edge_attr + (size_t)eg  * 128;

    const uint32_t offA[2] = {
        sbase + (OFF_A0 + arow * A_STR + aq * 8) * 4u,
        sbase + (OFF_A1 + arow * A_STR + aq * 8) * 4u };
    const uint32_t bdst[2] = { sbase + OFF_B0 * 4u, sbase + OFF_B1 * 4u };
    const uint32_t mbar[2] = { mb0, mb1 };

    auto issue_a = [&](int ch) {
        const int buf = ch & 1;
        const int sel = ch >> 2;
        const float* ab = (sel == 0) ? base_s : ((sel == 1) ? base_r : base_e);
        const float* asrc = ab + (ch & 3) * 32 + aq * 8;
        cp16(offA[buf], asrc);
        cp16(offA[buf] + 16, asrc + 4);
        CP_COMMIT();
    };

    __syncthreads();   // mbarrier init + prm visible

    float acc[2][4][4];
    #pragma unroll
    for (int i = 0; i < 2; ++i)
        #pragma unroll
        for (int j = 0; j < 4; ++j)
            #pragma unroll
            for (int c = 0; c < 4; ++c) acc[i][j][c] = 0.f;

    // prologue: chunk 0
    issue_a(0);
    if (tid == 0) {
        MBAR_ARRIVE_EXPECT(mb0, B_CHUNK_BYTES);
        BULK_G2S(bdst[0], g_W1p, B_CHUNK_BYTES, mb0);
    }

    const int halfsel = wn >> 6;              // which 64-wide half
    const int jsel    = (wn & 32) >> 5;       // which j-quarter
    int ph0 = 0, ph1 = 0;

    // ======================= GEMM1: 12 chunks of k=32 =======================
    #pragma unroll 2
    for (int ch = 0; ch < 12; ++ch) {
        const int b = ch & 1;
        CP_WAIT0();
        __syncthreads();
        if (ch < 11) {
            issue_a(ch + 1);
            if (tid == 0) {
                MBAR_ARRIVE_EXPECT(mbar[b ^ 1], B_CHUNK_BYTES);
                BULK_G2S(bdst[b ^ 1], g_W1p + (size_t)(ch + 1) * B_CHUNK_FL,
                         B_CHUNK_BYTES, mbar[b ^ 1]);
            }
        } else {
            if (tid == 0) {
                MBAR_ARRIVE_EXPECT(mb0, B_CHUNK_BYTES);
                BULK_G2S(bdst[0], g_W2p, B_CHUNK_BYTES, mb0);
            }
        }
        if (b == 0) { MBAR_WAIT(mb0, ph0); ph0 ^= 1; }
        else        { MBAR_WAIT(mb1, ph1); ph1 ^= 1; }

        const uint32_t* Af = reinterpret_cast<const uint32_t*>(
                                 smem + (b ? OFF_A1 : OFF_A0)) + (wm + g) * A_STR;
        const uint4* Bq = reinterpret_cast<const uint4*>(smem + (b ? OFF_B1 : OFF_B0));
        #pragma unroll
        for (int ks = 0; ks < 4; ++ks) {
            const int ka = ks * 8 + tig;
            const uint4* bp = Bq + (size_t)((ks * 2 + halfsel) * 4 + tig) * 33
                              + g * 4 + jsel * 2;
            uint4 r0 = bp[0], r1 = bp[1];
            uint32_t av[2][4];
            #pragma unroll
            for (int i = 0; i < 2; ++i) {
                // raw fp32 bits; tf32 MMA truncates low mantissa bits in HW
                av[i][0] = Af[(16 * i)     * A_STR + ka];
                av[i][1] = Af[(16 * i + 8) * A_STR + ka];
                av[i][2] = Af[(16 * i)     * A_STR + ka + 4];
                av[i][3] = Af[(16 * i + 8) * A_STR + ka + 4];
            }
            #pragma unroll
            for (int i = 0; i < 2; ++i) {
                mma8(acc[i][0], av[i][0], av[i][1], av[i][2], av[i][3], r0.x, r0.y);
                mma8(acc[i][1], av[i][0], av[i][1], av[i][2], av[i][3], r0.z, r0.w);
                mma8(acc[i][2], av[i][0], av[i][1], av[i][2], av[i][3], r1.x, r1.y);
                mma8(acc[i][3], av[i][0], av[i][1], av[i][2], av[i][3], r1.z, r1.w);
            }
        }
    }
    __syncthreads();   // GEMM1 reads done; A region free for H

    // ---- H = relu(acc + b1) -> H[m][k] tf32 (uint2 pairs; W2(0) in flight)
    {
        uint32_t* Hsu = reinterpret_cast<uint32_t*>(smem + OFF_H);
        #pragma unroll
        for (int i = 0; i < 2; ++i) {
            const int r0 = wm + 16 * i + g;
            #pragma unroll
            for (int j = 0; j < 4; ++j) {
                const int n0 = wn + 8 * j + 2 * tig;
                float bj0 = prm[n0], bj1 = prm[n0 + 1];
                uint2 h01 = make_uint2(f2tf(fmaxf(acc[i][j][0] + bj0, 0.f)),
                                       f2tf(fmaxf(acc[i][j][1] + bj1, 0.f)));
                uint2 h23 = make_uint2(f2tf(fmaxf(acc[i][j][2] + bj0, 0.f)),
                                       f2tf(fmaxf(acc[i][j][3] + bj1, 0.f)));
                *reinterpret_cast<uint2*>(&Hsu[r0 * H_STR + n0])       = h01;
                *reinterpret_cast<uint2*>(&Hsu[(r0 + 8) * H_STR + n0]) = h23;
            }
        }
    }

    #pragma unroll
    for (int i = 0; i < 2; ++i)
        #pragma unroll
        for (int j = 0; j < 4; ++j)
            #pragma unroll
            for (int c = 0; c < 4; ++c) acc[i][j][c] = 0.f;

    // ======================= GEMM2: 4 chunks of k=32 =======================
    #pragma unroll 2
    for (int ch = 0; ch < 4; ++ch) {
        const int b = ch & 1;
        __syncthreads();
        if (ch < 3 && tid == 0) {
            MBAR_ARRIVE_EXPECT(mbar[b ^ 1], B_CHUNK_BYTES);
            BULK_G2S(bdst[b ^ 1], g_W2p + (size_t)(ch + 1) * B_CHUNK_FL,
                     B_CHUNK_BYTES, mbar[b ^ 1]);
        }
        if (b == 0) { MBAR_WAIT(mb0, ph0); ph0 ^= 1; }
        else        { MBAR_WAIT(mb1, ph1); ph1 ^= 1; }

        const uint32_t* Hf = reinterpret_cast<const uint32_t*>(smem + OFF_H)
                             + (wm + g) * H_STR + ch * 32;
        const uint4* Bq = reinterpret_cast<const uint4*>(smem + (b ? OFF_B1 : OFF_B0));
        #pragma unroll
        for (int ks = 0; ks < 4; ++ks) {
            const int ka = ks * 8 + tig;
            const uint4* bp = Bq + (size_t)((ks * 2 + halfsel) * 4 + tig) * 33
                              + g * 4 + jsel * 2;
            uint4 r0 = bp[0], r1 = bp[1];
            uint32_t av[2][4];
            #pragma unroll
            for (int i = 0; i < 2; ++i) {
                av[i][0] = Hf[(16 * i)     * H_STR + ka];
                av[i][1] = Hf[(16 * i + 8) * H_STR + ka];
                av[i][2] = Hf[(16 * i)     * H_STR + ka + 4];
                av[i][3] = Hf[(16 * i + 8) * H_STR + ka + 4];
            }
            #pragma unroll
            for (int i = 0; i < 2; ++i) {
                mma8(acc[i][0], av[i][0], av[i][1], av[i][2], av[i][3], r0.x, r0.y);
                mma8(acc[i][1], av[i][0], av[i][1], av[i][2], av[i][3], r0.z, r0.w);
                mma8(acc[i][2], av[i][0], av[i][1], av[i][2], av[i][3], r1.x, r1.y);
                mma8(acc[i][3], av[i][0], av[i][1], av[i][2], av[i][3], r1.z, r1.w);
            }
        }
    }

    // ======================= LayerNorm epilogue (4 column partials) =========
    #pragma unroll
    for (int i = 0; i < 2; ++i) {
        float s0 = 0.f, q0 = 0.f, s1 = 0.f, q1 = 0.f;
        #pragma unroll
        for (int j = 0; j < 4; ++j) {
            const int n0 = wn + 8 * j + 2 * tig;
            float v0 = acc[i][j][0] + prm[128 + n0];
            float v1 = acc[i][j][1] + prm[128 + n0 + 1];
            float v2 = acc[i][j][2] + prm[128 + n0];
            float v3 = acc[i][j][3] + prm[128 + n0 + 1];
            acc[i][j][0] = v0; acc[i][j][1] = v1; acc[i][j][2] = v2; acc[i][j][3] = v3;
            s0 += v0 + v1; q0 += v0 * v0 + v1 * v1;
            s1 += v2 + v3; q1 += v2 * v2 + v3 * v3;
        }
        #pragma unroll
        for (int m = 1; m < 4; m <<= 1) {
            s0 += __shfl_xor_sync(0xffffffffu, s0, m);
            q0 += __shfl_xor_sync(0xffffffffu, q0, m);
            s1 += __shfl_xor_sync(0xffffffffu, s1, m);
            q1 += __shfl_xor_sync(0xffffffffu, q1, m);
        }
        if (tig == 0) {
            const int r0 = wm + 16 * i + g;
            ps[wc * 64 + r0]           = s0;
            ps[wc * 64 + r0 + 8]       = s1;
            ps[256 + wc * 64 + r0]     = q0;
            ps[256 + wc * 64 + r0 + 8] = q1;
        }
    }
    __syncthreads();

    #pragma unroll
    for (int i = 0; i < 2; ++i) {
        const int r0 = wm + 16 * i + g;
        const int r1 = r0 + 8;
        float s0 = ps[r0] + ps[64 + r0] + ps[128 + r0] + ps[192 + r0];
        float q0 = ps[256 + r0] + ps[320 + r0] + ps[384 + r0] + ps[448 + r0];
        float s1 = ps[r1] + ps[64 + r1] + ps[128 + r1] + ps[192 + r1];
        float q1 = ps[256 + r1] + ps[320 + r1] + ps[384 + r1] + ps[448 + r1];
        const float mu0 = s0 * (1.f / 128.f);
        const float mu1 = s1 * (1.f / 128.f);
        const float rs0 = rsqrtf(q0 * (1.f / 128.f) - mu0 * mu0 + 1e-5f);
        const float rs1 = rsqrtf(q1 * (1.f / 128.f) - mu1 * mu1 + 1e-5f);
        const int eg0 = eb + r0;
        const int eg1 = eb + r1;
        if (eg0 < E) {
            float* orow = out + (size_t)eg0 * 128;
            #pragma unroll
            for (int j = 0; j < 4; ++j) {
                const int n0 = wn + 8 * j + 2 * tig;
                float o0 = (acc[i][j][0] - mu0) * rs0 * prm[256 + n0]     + prm[384 + n0];
                float o1 = (acc[i][j][1] - mu0) * rs0 * prm[256 + n0 + 1] + prm[384 + n0 + 1];
                *reinterpret_cast<float2*>(orow + n0) = make_float2(o0, o1);
            }
        }
        if (eg1 < E) {
            float* orow = out + (size_t)eg1 * 128;
            #pragma unroll
            for (int j = 0; j < 4; ++j) {
                const int n0 = wn + 8 * j + 2 * tig;
                float o2 = (acc[i][j][2] - mu1) * rs1 * prm[256 + n0]     + prm[384 + n0];
                float o3 = (acc[i][j][3] - mu1) * rs1 * prm[256 + n0 + 1] + prm[384 + n0 + 1];
                *reinterpret_cast<float2*>(orow + n0) = make_float2(o2, o3);
            }
        }
    }
}

extern "C" void kernel_launch(void* const* d_in, const int* in_sizes, int n_in,
                              void* d_out, int out_size)
{
    (void)n_in; (void)out_size;
    const float* node_attr = (const float*)d_in[0];
    const float* edge_attr = (const float*)d_in[1];
    const int*   senders   = (const int*)  d_in[2];
    const int*   receivers = (const int*)  d_in[3];
    const float* W1        = (const float*)d_in[4];
    const float* b1        = (const float*)d_in[5];
    const float* W2        = (const float*)d_in[6];
    const float* b2        = (const float*)d_in[7];
    const float* ln_gamma  = (const float*)d_in[8];
    const float* ln_beta   = (const float*)d_in[9];
    float* out = (float*)d_out;

    const int E = in_sizes[2];

    pack_weights<<<256, 256>>>(W1, W2);

    cudaFuncSetAttribute(edge_block_mma,
                         cudaFuncAttributeMaxDynamicSharedMemorySize, SMEM_BYTES);

    const int grid = (E + CTA_M - 1) / CTA_M;
    edge_block_mma<<<grid, THREADS, SMEM_BYTES>>>(
        node_attr, edge_attr, senders, receivers,
        b1, b2, ln_gamma, ln_beta, out, E);
}